// round 1
// baseline (speedup 1.0000x reference)
#include <cuda_runtime.h>

#define BN 16
#define CN 1024
#define TN 16
#define PN 360          // H*W = 12*30
#define KN 120
#define NCHUNK 16
#define CPC 64          // CN / NCHUNK
#define OUTROWS 482     // 1 + 120 + 1 + 360

// scratch (no allocations allowed)
__device__ float g_partial[BN][NCHUNK][PN];
__device__ int   g_rank[BN][PN];

// ---------------------------------------------------------------------------
// Kernel A: partial dot products for frame 0.
// s[b][p] = sum_c cls[b,0,c] * x[b,c,0,p], split over 16 c-chunks for SM
// occupancy. Loads coalesced across p (adjacent threads -> adjacent floats).
// ---------------------------------------------------------------------------
__global__ void scores_partial_kernel(const float* __restrict__ x,
                                      const float* __restrict__ cls) {
    int b = blockIdx.x, chunk = blockIdx.y;
    int p = threadIdx.x;
    if (p >= PN) return;
    const size_t cstride = (size_t)TN * PN;                       // stride between c planes
    const float* xb = x + ((size_t)b * CN + (size_t)chunk * CPC) * cstride + p;  // t = 0
    const float* cb = cls + (size_t)b * TN * CN + chunk * CPC;                   // cls[b,0,*]
    float acc = 0.f;
#pragma unroll 8
    for (int c = 0; c < CPC; ++c)
        acc = fmaf(cb[c], xb[(size_t)c * cstride], acc);
    g_partial[b][chunk][p] = acc;
}

// ---------------------------------------------------------------------------
// Kernel B: reduce partials -> score, compute exact stable descending rank
// (rank = #strictly greater + #equal with smaller index), and copy the two
// cls rows into the output. Ranks form a permutation of 0..359, so ranks
// 0..119 select exactly the reference's stable top-K in order.
// ---------------------------------------------------------------------------
__global__ void rank_kernel(const float* __restrict__ cls, float* __restrict__ out) {
    int b = blockIdx.x;
    int p = threadIdx.x;                 // 384 threads
    __shared__ float s[PN];
    float v = 0.f;
    if (p < PN) {
#pragma unroll
        for (int k = 0; k < NCHUNK; ++k) v += g_partial[b][k][p];
        s[p] = v;
    }
    __syncthreads();
    if (p < PN) {
        int cnt = 0;
        for (int q = 0; q < PN; ++q) {
            float sq = s[q];
            cnt += (sq > v) || (sq == v && q < p);
        }
        g_rank[b][p] = cnt;
    }
    // cls rows: out[b,0,:] = cls[b,0,:], out[b,121,:] = cls[b,1,:]
    for (int c = threadIdx.x; c < CN; c += blockDim.x) {
        out[((size_t)b * OUTROWS + 0)   * CN + c] = cls[((size_t)b * TN + 0) * CN + c];
        out[((size_t)b * OUTROWS + 121) * CN + c] = cls[((size_t)b * TN + 1) * CN + c];
    }
}

// ---------------------------------------------------------------------------
// Kernel C: tiled transpose + scatter.
//   frame 0: out[b, 1+rank[p], c] = x[b,c,0,p]   (only rank < K)
//   frame 1: out[b, 122+p,    c] = x[b,c,1,p]
// 32x32 smem tile: reads coalesced along p, writes coalesced along c.
// ---------------------------------------------------------------------------
__global__ void assemble_kernel(const float* __restrict__ x, float* __restrict__ out) {
    __shared__ float tile[32][33];
    int b     = blockIdx.z;
    int frame = blockIdx.y >> 5;
    int c0    = (blockIdx.y & 31) * 32;
    int p0    = blockIdx.x * 32;
    int tx = threadIdx.x, ty = threadIdx.y;

#pragma unroll
    for (int i = 0; i < 4; ++i) {
        int cc = ty + i * 8;
        int p  = p0 + tx;
        float vv = 0.f;
        if (p < PN)
            vv = x[(((size_t)b * CN + (c0 + cc)) * TN + frame) * (size_t)PN + p];
        tile[cc][tx] = vv;
    }
    __syncthreads();

#pragma unroll
    for (int i = 0; i < 4; ++i) {
        int pp = ty + i * 8;
        int p  = p0 + pp;
        if (p >= PN) continue;
        int c = c0 + tx;
        int row;
        if (frame == 0) {
            int r = g_rank[b][p];
            if (r >= KN) continue;
            row = 1 + r;
        } else {
            row = 122 + p;
        }
        out[((size_t)b * OUTROWS + row) * CN + c] = tile[tx][pp];
    }
}

extern "C" void kernel_launch(void* const* d_in, const int* in_sizes, int n_in,
                              void* d_out, int out_size) {
    const float* x   = (const float*)d_in[0];   // [16,1024,16,12,30] f32
    const float* cls = (const float*)d_in[1];   // [16,16,1024] f32
    float* out = (float*)d_out;                 // [16,482,1024] f32

    scores_partial_kernel<<<dim3(BN, NCHUNK), 384>>>(x, cls);
    rank_kernel<<<BN, 384>>>(cls, out);
    // grid: x = 12 p-tiles (ceil 360/32), y = frame(2) * 32 c-tiles, z = batch
    assemble_kernel<<<dim3(12, 64, BN), dim3(32, 8)>>>(x, out);
}